// round 1
// baseline (speedup 1.0000x reference)
#include <cuda_runtime.h>

// Fused per-variable MLP:
//   h0 = leaky( (w0[t] ⊙ mask_t) @ x_b + b0[t] )   K=128 -> 64
//   h1 = leaky( w1[t] @ h0 + b1[t] )               K=64  -> 64
//   out= w2[t] @ h1 + b2[t]                        K=64  -> 2
// One CTA = (one variable t) x (128 batch rows). All intermediates in SMEM.

#define DD    128   // input dim / num variables
#define HH    64    // hidden
#define OO    2     // output dim
#define BT    128   // batch rows per CTA
#define NT    256   // threads per CTA
#define SLOPE 0.01f

// SMEM layout (floats)
#define OFF_X   0                        // sX  [BT][128]          16384
#define OFF_W0  (OFF_X  + BT*DD)         // sW0t[128][65] (k-major) 8320
#define OFF_W1  (OFF_W0 + DD*65)         // sW1t[64][65]            4160
#define OFF_H   (OFF_W1 + HH*65)         // sH  [BT][64]            8192
#define OFF_H2  (OFF_H  + BT*64)         // sH2 [BT][66]            8448
#define OFF_W2  (OFF_H2 + BT*66)         // sW2 [2][64]              128
#define SMEM_FLOATS (OFF_W2 + OO*64)     // = 45632 floats = 182528 B

__global__ void __launch_bounds__(NT, 1)
fused_mlp_kernel(const float* __restrict__ x,
                 const float* __restrict__ w0,
                 const float* __restrict__ w1,
                 const float* __restrict__ w2,
                 const float* __restrict__ b0,
                 const float* __restrict__ b1,
                 const float* __restrict__ b2,
                 float* __restrict__ out)
{
    extern __shared__ float s[];
    const int t     = blockIdx.x;           // variable index 0..127
    const int brow0 = blockIdx.y * BT;      // batch tile origin
    const int tid   = threadIdx.x;
    const int w     = tid >> 5;             // warp 0..7
    const int l     = tid & 31;             // lane

    // ---- stage x tile: [BT][128], coalesced float4 ----
    {
        const float4* xg  = reinterpret_cast<const float4*>(x + (size_t)brow0 * DD);
        float4*       sx4 = reinterpret_cast<float4*>(s + OFF_X);
        #pragma unroll
        for (int i = tid; i < BT * DD / 4; i += NT) sx4[i] = xg[i];
    }
    // ---- stage w0[t] transposed to [k][i], stride 65, masked at j==t ----
    {
        const float* w0g = w0 + (size_t)t * (HH * DD);
        #pragma unroll
        for (int idx = tid; idx < HH * DD; idx += NT) {
            int i = idx >> 7;          // output unit
            int j = idx & 127;         // input var
            float v = (j == t) ? 0.0f : w0g[idx];
            s[OFF_W0 + j * 65 + i] = v;
        }
    }
    // ---- stage w1[t] transposed to [k][i], stride 65 ----
    {
        const float* w1g = w1 + (size_t)t * (HH * HH);
        #pragma unroll
        for (int idx = tid; idx < HH * HH; idx += NT) {
            int i = idx >> 6;
            int j = idx & 63;
            s[OFF_W1 + j * 65 + i] = w1g[idx];
        }
    }
    // ---- stage w2[t]: [2][64] linear ----
    if (tid < OO * HH) s[OFF_W2 + tid] = w2[(size_t)t * OO * HH + tid];
    __syncthreads();

    // =============== layer 0: [BT x 64] = sX[BT x 128] * W0^T ===============
    // warp w: rows r0..r0+15; lane l: cols l and l+32
    {
        const int   r0 = w * 16;
        const float bia = b0[t * HH + l];
        const float bib = b0[t * HH + l + 32];
        float acc0[16], acc1[16];
        #pragma unroll
        for (int j = 0; j < 16; j++) { acc0[j] = bia; acc1[j] = bib; }

        const float* sx = s + OFF_X + r0 * DD;
        const float* sw = s + OFF_W0;
        #pragma unroll 4
        for (int k = 0; k < DD; k++) {
            const float wa = sw[k * 65 + l];        // conflict-free
            const float wb = sw[k * 65 + l + 32];
            #pragma unroll
            for (int j = 0; j < 16; j++) {
                const float xv = sx[j * DD + k];    // warp broadcast
                acc0[j] = fmaf(xv, wa, acc0[j]);
                acc1[j] = fmaf(xv, wb, acc1[j]);
            }
        }
        float* sh = s + OFF_H + r0 * 64;
        #pragma unroll
        for (int j = 0; j < 16; j++) {
            float v0 = acc0[j]; v0 = (v0 > 0.0f) ? v0 : SLOPE * v0;
            float v1 = acc1[j]; v1 = (v1 > 0.0f) ? v1 : SLOPE * v1;
            sh[j * 64 + l]      = v0;               // conflict-free
            sh[j * 64 + l + 32] = v1;
        }
    }
    __syncthreads();

    // =============== layer 1: [BT x 64] = sH[BT x 64] * W1^T ===============
    {
        const int   r0 = w * 16;
        const float bia = b1[t * HH + l];
        const float bib = b1[t * HH + l + 32];
        float acc0[16], acc1[16];
        #pragma unroll
        for (int j = 0; j < 16; j++) { acc0[j] = bia; acc1[j] = bib; }

        const float* sh = s + OFF_H + r0 * 64;
        const float* sw = s + OFF_W1;
        #pragma unroll 4
        for (int k = 0; k < HH; k++) {
            const float wa = sw[k * 65 + l];
            const float wb = sw[k * 65 + l + 32];
            #pragma unroll
            for (int j = 0; j < 16; j++) {
                const float hv = sh[j * 64 + k];    // warp broadcast
                acc0[j] = fmaf(hv, wa, acc0[j]);
                acc1[j] = fmaf(hv, wb, acc1[j]);
            }
        }
        float* sh2 = s + OFF_H2 + r0 * 66;
        #pragma unroll
        for (int j = 0; j < 16; j++) {
            float v0 = acc0[j]; v0 = (v0 > 0.0f) ? v0 : SLOPE * v0;
            float v1 = acc1[j]; v1 = (v1 > 0.0f) ? v1 : SLOPE * v1;
            sh2[j * 66 + l]      = v0;
            sh2[j * 66 + l + 32] = v1;
        }
    }
    __syncthreads();

    // =============== layer 2: [BT x 2] = sH2 * W2^T, one output/thread ====
    {
        const int row = tid >> 1;
        const int o   = tid & 1;
        const float* sh2 = s + OFF_H2 + row * 66;
        const float* sw2 = s + OFF_W2 + o * 64;
        float acc = b2[t * OO + o];
        #pragma unroll
        for (int k = 0; k < HH; k++) acc = fmaf(sh2[k], sw2[k], acc);
        out[(size_t)(brow0 + row) * (DD * OO) + t * OO + o] = acc;
    }
}

extern "C" void kernel_launch(void* const* d_in, const int* in_sizes, int n_in,
                              void* d_out, int out_size)
{
    const float* x  = (const float*)d_in[0];   // (8192,128)
    const float* w0 = (const float*)d_in[1];   // (128,64,128)
    const float* w1 = (const float*)d_in[2];   // (128,64,64)
    const float* w2 = (const float*)d_in[3];   // (128,2,64)
    const float* b0 = (const float*)d_in[4];   // (128,64)
    const float* b1 = (const float*)d_in[5];   // (128,64)
    const float* b2 = (const float*)d_in[6];   // (128,2)
    float* out = (float*)d_out;                // (8192,128,2)

    const int B = in_sizes[0] / DD;            // 8192

    static bool attr_set = false;
    if (!attr_set) {
        cudaFuncSetAttribute(fused_mlp_kernel,
                             cudaFuncAttributeMaxDynamicSharedMemorySize,
                             SMEM_FLOATS * (int)sizeof(float));
        attr_set = true;
    }

    dim3 grid(DD, B / BT);   // (128, 64)
    fused_mlp_kernel<<<grid, NT, SMEM_FLOATS * (int)sizeof(float)>>>(
        x, w0, w1, w2, b0, b1, b2, out);
}